// round 2
// baseline (speedup 1.0000x reference)
#include <cuda_runtime.h>

// FIRApply: y[t] = sum_{k=0}^{15} b[k] * x[t-k], zero initial state.
// x: [64, 480000] f32, b: [16] f32, y: [64, 480000] f32.

#define BATCH  64
#define T_LEN  480000
#define NTAPS  16
#define OPT    16         // outputs per thread
#define TPB    128        // threads per block
#define OPB    (OPT*TPB)  // outputs per block = 2048

__global__ __launch_bounds__(TPB, 6)
void fir_kernel(const float* __restrict__ x,
                const float* __restrict__ b,
                float* __restrict__ y)
{
    const int row = blockIdx.y;
    const int t0  = blockIdx.x * OPB + threadIdx.x * OPT;  // first output idx
    if (t0 >= T_LEN) return;

    const float* __restrict__ xr = x + (long long)row * T_LEN;
    float*       __restrict__ yr = y + (long long)row * T_LEN;

    // taps -> registers via 4 vector loads (b is 16 floats, 16B-aligned buffer)
    float bb[NTAPS];
#pragma unroll
    for (int c = 0; c < 4; c++) {
        float4 v = __ldg(reinterpret_cast<const float4*>(b) + c);
        bb[4*c+0] = v.x; bb[4*c+1] = v.y; bb[4*c+2] = v.z; bb[4*c+3] = v.w;
    }

    // window w[q] = x[t0 - 16 + q], q = 0..31  (covers x[t0-16 .. t0+15])
    float w[32];
    const int g0 = t0 - 16;           // multiple of 16 -> 64B aligned
    if (g0 >= 0) {
        // T_LEN % 16 == 0 and t0 < T_LEN  =>  t0+15 < T_LEN: full fast path
#pragma unroll
        for (int c = 0; c < 8; c++) {
            float4 v = *reinterpret_cast<const float4*>(xr + g0 + 4 * c);
            w[4*c+0] = v.x; w[4*c+1] = v.y; w[4*c+2] = v.z; w[4*c+3] = v.w;
        }
    } else {
        // left edge of the row (t0 == 0 only): zero-pad history
#pragma unroll
        for (int q = 0; q < 32; q++) {
            const int g = g0 + q;
            w[q] = (g >= 0) ? xr[g] : 0.0f;
        }
    }

    // y[t0+o] = sum_k bb[k] * w[o + 16 - k],  index range 1..31
    float acc[OPT];
#pragma unroll
    for (int o = 0; o < OPT; o++) {
        float s = 0.0f;
#pragma unroll
        for (int k = 0; k < NTAPS; k++)
            s = fmaf(bb[k], w[o + 16 - k], s);
        acc[o] = s;
    }

    // four aligned float4 stores
#pragma unroll
    for (int c = 0; c < 4; c++) {
        float4 s = make_float4(acc[4*c+0], acc[4*c+1], acc[4*c+2], acc[4*c+3]);
        *reinterpret_cast<float4*>(yr + t0 + 4 * c) = s;
    }
}

extern "C" void kernel_launch(void* const* d_in, const int* in_sizes, int n_in,
                              void* d_out, int out_size)
{
    const float* x = (const float*)d_in[0];
    const float* b = (const float*)d_in[1];
    float* y = (float*)d_out;

    dim3 grid((T_LEN + OPB - 1) / OPB, BATCH);  // (235, 64)
    fir_kernel<<<grid, TPB>>>(x, b, y);
}

// round 3
// speedup vs baseline: 1.4805x; 1.4805x over previous
#include <cuda_runtime.h>

// FIRApply: y[t] = sum_{k=0}^{15} b[k] * x[t-k], zero initial state.
// x: [64, 480000] f32, b: [16] f32, y: [64, 480000] f32.

#define BATCH  64
#define T_LEN  480000
#define NTAPS  16
#define OPT    8          // outputs per thread
#define TPB    256        // threads per block
#define OPB    (OPT*TPB)  // outputs per block = 2048

// Padded smem layout: +4 floats per 32 logical floats (16B per 128B block).
// Makes both the staging stores (16B thread stride) and the window reads
// (32B thread stride) hit all 32 banks exactly once per phase.
#define SPAD(l) ((l) + ((((unsigned)(l)) >> 5) << 2))

#define STAGE_F4   ((OPB + 16) / 4)                 // 516 float4 loads per tile
#define SMEM_FLOATS (SPAD(OPB + 16 - 4) + 4)        // covers last float4

__global__ __launch_bounds__(TPB)
void fir_kernel(const float* __restrict__ x,
                const float* __restrict__ b,
                float* __restrict__ y)
{
    __shared__ float sx[SMEM_FLOATS];

    const int row  = blockIdx.y;
    const int tile = blockIdx.x * OPB;              // first output of this tile
    const float* __restrict__ xr = x + (long long)row * T_LEN;
    float*       __restrict__ yr = y + (long long)row * T_LEN;

    // ---- Stage tile + left halo: logical float l <-> x[tile - 16 + l] ----
    // g is a multiple of 4 and T_LEN % 4 == 0, so each float4 is entirely
    // in-range or entirely out (zero-fill handles both the t<0 history and
    // the ragged right edge of the last tile).
#pragma unroll
    for (int it = 0; it < 3; it++) {
        int f = threadIdx.x + it * TPB;             // float4 index 0..515
        if (f < STAGE_F4) {
            int l = 4 * f;
            int g = tile - 16 + l;
            float4 v = make_float4(0.f, 0.f, 0.f, 0.f);
            if (g >= 0 && g < T_LEN)
                v = *reinterpret_cast<const float4*>(xr + g);
            *reinterpret_cast<float4*>(&sx[SPAD(l)]) = v;
        }
    }

    // taps -> registers (uniform broadcast, 4 wavefronts total)
    float bb[NTAPS];
#pragma unroll
    for (int c = 0; c < 4; c++) {
        float4 v = __ldg(reinterpret_cast<const float4*>(b) + c);
        bb[4*c+0] = v.x; bb[4*c+1] = v.y; bb[4*c+2] = v.z; bb[4*c+3] = v.w;
    }

    __syncthreads();

    const int t0 = tile + threadIdx.x * OPT;
    if (t0 >= T_LEN) return;

    // ---- Window from smem: w[q] = x[t0 - 16 + q], q = 0..23 ----
    float w[24];
#pragma unroll
    for (int c = 0; c < 6; c++) {
        int l = OPT * threadIdx.x + 4 * c;          // logical float index
        float4 v = *reinterpret_cast<const float4*>(&sx[SPAD(l)]);
        w[4*c+0] = v.x; w[4*c+1] = v.y; w[4*c+2] = v.z; w[4*c+3] = v.w;
    }

    // ---- y[t0+o] = sum_k bb[k] * w[o + 16 - k] ----
    float acc[OPT];
#pragma unroll
    for (int o = 0; o < OPT; o++) {
        float s = 0.0f;
#pragma unroll
        for (int k = 0; k < NTAPS; k++)
            s = fmaf(bb[k], w[o + 16 - k], s);
        acc[o] = s;
    }

    // two aligned float4 stores (t0 multiple of 8, T_LEN % 8 == 0 -> in range)
    *reinterpret_cast<float4*>(yr + t0)     = make_float4(acc[0], acc[1], acc[2], acc[3]);
    *reinterpret_cast<float4*>(yr + t0 + 4) = make_float4(acc[4], acc[5], acc[6], acc[7]);
}

extern "C" void kernel_launch(void* const* d_in, const int* in_sizes, int n_in,
                              void* d_out, int out_size)
{
    const float* x = (const float*)d_in[0];
    const float* b = (const float*)d_in[1];
    float* y = (float*)d_out;

    dim3 grid((T_LEN + OPB - 1) / OPB, BATCH);  // (235, 64)
    fir_kernel<<<grid, TPB>>>(x, b, y);
}

// round 5
// speedup vs baseline: 1.8955x; 1.2804x over previous
#include <cuda_runtime.h>

// FIRApply: y[t] = sum_{k=0}^{15} b[k] * x[t-k], zero initial state.
// x: [64, 480000] f32, b: [16] f32, y: [64, 480000] f32.

#define BATCH  64
#define T_LEN  480000
#define NTAPS  16
#define OPT    8          // outputs per thread
#define TPB    256        // threads per block
#define OPB    (OPT*TPB)  // outputs per block = 2048

// Taps live in constant memory: reads go through the constant/uniform port,
// generating ZERO L1TEX wavefronts (the R1 profile showed tap LDGs were ~20%
// of all L1 wavefronts). Filled by a capture-legal D2D memcpyToSymbol.
__constant__ float c_b[NTAPS];

__global__ __launch_bounds__(TPB)
void fir_kernel(const float* __restrict__ x,
                float* __restrict__ y)
{
    const int row = blockIdx.y;
    const int t0  = blockIdx.x * OPB + threadIdx.x * OPT;  // first output idx
    if (t0 >= T_LEN) return;

    const float* __restrict__ xr = x + (long long)row * T_LEN;
    float*       __restrict__ yr = y + (long long)row * T_LEN;

    // window w[q] = x[t0 - 16 + q], q = 0..23  (covers x[t0-15 .. t0+7])
    float w[24];
    const int g0 = t0 - 16;           // multiple of 8 -> 32B aligned
    if (g0 >= 0) {
        // T_LEN % 8 == 0 and t0 < T_LEN  =>  t0+7 < T_LEN: full fast path
#pragma unroll
        for (int c = 0; c < 6; c++) {
            float4 v = __ldg(reinterpret_cast<const float4*>(xr + g0 + 4 * c));
            w[4*c+0] = v.x; w[4*c+1] = v.y; w[4*c+2] = v.z; w[4*c+3] = v.w;
        }
    } else {
        // left edge of the row (t0 < 16): zero-pad history
#pragma unroll
        for (int q = 0; q < 24; q++) {
            const int g = g0 + q;
            w[q] = (g >= 0) ? xr[g] : 0.0f;
        }
    }

    // y[t0+o] = sum_k c_b[k] * w[o + 16 - k]
    float acc[OPT];
#pragma unroll
    for (int o = 0; o < OPT; o++) {
        float s = 0.0f;
#pragma unroll
        for (int k = 0; k < NTAPS; k++)
            s = fmaf(c_b[k], w[o + 16 - k], s);
        acc[o] = s;
    }

    // two aligned float4 stores
    *reinterpret_cast<float4*>(yr + t0)     = make_float4(acc[0], acc[1], acc[2], acc[3]);
    *reinterpret_cast<float4*>(yr + t0 + 4) = make_float4(acc[4], acc[5], acc[6], acc[7]);
}

extern "C" void kernel_launch(void* const* d_in, const int* in_sizes, int n_in,
                              void* d_out, int out_size)
{
    const float* x = (const float*)d_in[0];
    const float* b = (const float*)d_in[1];
    float* y = (float*)d_out;

    // Capture-legal: async device->device copy into the constant bank.
    cudaMemcpyToSymbolAsync(c_b, b, NTAPS * sizeof(float), 0,
                            cudaMemcpyDeviceToDevice);

    dim3 grid((T_LEN + OPB - 1) / OPB, BATCH);  // (235, 64)
    fir_kernel<<<grid, TPB>>>(x, y);
}